// round 17
// baseline (speedup 1.0000x reference)
#include <cuda_runtime.h>
#include <cuda_bf16.h>
#include <math.h>
#include <stdint.h>

#define DIM     2048
#define NE      128
#define KSEL    4
#define BM      128     // tokens per tile (CTA)
#define KC      32      // K elems per chunk (2 k16-steps)
#define NCHALF  32      // chunks per half-K CTA
#define THREADS 256
#define LST     129     // logits smem stride

#define A12BLK  33                    // 16B slots per (rg,ks) block
#define A3BLK   34                    // 8B slots per block (even -> 16B-aligned pairs)
#define A12SZ   (32 * A12BLK * 16)    // 16896
#define A3SZ    (32 * A3BLK * 8)      // 8704
#define ABUF    (A12SZ + A3SZ)        // 25600
#define B12SZ   16384
#define B3SZ    8192
#define BCH     (B12SZ + B3SZ)        // 24576
#define BOFF    (2 * ABUF)            // 51200
#define SOFF    (BOFF + 2 * BCH)      // 100352
#define SMEM_TOTAL (SOFF + 64 * THREADS * 4)   // 165888
#define RSMEM   (BM * LST * 4)        // 66048

// Chunk-major bf16 3-split W: per chunk [B12 16KB | B3 8KB].
// B12 entry (uint4) at ((n8*2+ks)*32+lane): {B1 pair(2t), B1 pair(2t+8), B2 pair(2t), B2 pair(2t+8)}
// B3  entry (uint2): {B3 pair(2t), B3 pair(2t+8)};  n = n8*8 + (lane>>2), t = lane&3
__device__ char g_Wb[64 * BCH];                  // 1.5 MB
__device__ float g_P[512 * 2 * BM * NE];         // 64 MB partial logits

__device__ __forceinline__ uint32_t smem_u32(const void* p) {
    uint32_t a;
    asm("{ .reg .u64 t; cvta.to.shared.u64 t, %1; cvt.u32.u64 %0, t; }" : "=r"(a) : "l"(p));
    return a;
}
__device__ __forceinline__ void cp_async16(uint32_t dst, const void* src) {
    asm volatile("cp.async.cg.shared.global [%0], [%1], 16;" :: "r"(dst), "l"(src) : "memory");
}
#define CP_COMMIT() asm volatile("cp.async.commit_group;" ::: "memory")
#define CP_WAIT0()  asm volatile("cp.async.wait_group 0;" ::: "memory")

// rn-round v to bf16, returned as the exact fp32 value of that bf16
__device__ __forceinline__ float bfr(float v) {
    unsigned short u;
    asm("cvt.rn.bf16.f32 %0, %1;" : "=h"(u) : "f"(v));
    return __uint_as_float((uint32_t)u << 16);
}
// pack two floats as bf16x2 (rn), lo -> low half (lower k index)
__device__ __forceinline__ uint32_t pk(float lo, float hi) {
    uint32_t r;
    asm("cvt.rn.bf16x2.f32 %0, %1, %2;" : "=r"(r) : "f"(hi), "f"(lo));
    return r;
}

__device__ __forceinline__ void mma_bf16(float c[4],
                                         unsigned a0, unsigned a1, unsigned a2, unsigned a3,
                                         unsigned b0, unsigned b1) {
    asm volatile(
        "mma.sync.aligned.m16n8k16.row.col.f32.bf16.bf16.f32 "
        "{%0,%1,%2,%3}, {%4,%5,%6,%7}, {%8,%9}, {%0,%1,%2,%3};\n"
        : "+f"(c[0]), "+f"(c[1]), "+f"(c[2]), "+f"(c[3])
        : "r"(a0), "r"(a1), "r"(a2), "r"(a3), "r"(b0), "r"(b1));
}

// One-time W -> bf16 3-split fragment tiles (65536 threads, 4 W elems each)
extern "C" __global__ void prep_w_kernel(const float* __restrict__ W) {
    int t    = blockIdx.x * 256 + threadIdx.x;   // 0..65535
    int lane = t & 31;
    int ks   = (t >> 5) & 1;
    int n8   = (t >> 6) & 15;
    int chunk = t >> 10;                          // 0..63
    int n  = n8 * 8 + (lane >> 2);
    int kb = chunk * 32 + ks * 16 + 2 * (lane & 3);
    float vv[4] = { W[n * DIM + kb],     W[n * DIM + kb + 1],
                    W[n * DIM + kb + 8], W[n * DIM + kb + 9] };
    float f1[4], f2[4], r2[4];
    #pragma unroll
    for (int j = 0; j < 4; j++) {
        f1[j] = bfr(vv[j]);
        float r = vv[j] - f1[j];
        f2[j] = bfr(r);
        r2[j] = r - f2[j];
    }
    char* base = g_Wb + (size_t)chunk * BCH;
    uint32_t idx = (uint32_t)((n8 * 2 + ks) * 32 + lane);
    ((uint4*)base)[idx] = make_uint4(pk(f1[0], f1[1]), pk(f1[2], f1[3]),
                                     pk(f2[0], f2[1]), pk(f2[2], f2[3]));
    ((uint2*)(base + B12SZ))[idx] = make_uint2(pk(r2[0], r2[1]), pk(r2[2], r2[3]));
}

// Split 16 prefetched x values (row = tid>>1, k16-step = tid&1) into bf16
// 3-split fragment slots. A12 slot(quad c) = {A1 pair(2c), A1 pair(2c+8),
// A2 pair(2c), A2 pair(2c+8)}; A3 slot(c) = {A3 pair(2c), A3 pair(2c+8)}.
__device__ __forceinline__ void store_a(char* abuf, const float4* v, int tid) {
    int row = tid >> 1, ks = tid & 1;
    int rg = row >> 3, tr = row & 7, rot = (tr + 2 * ks) & 7;
    const float* vf = (const float*)v;
    float f1[16], f2[16], r2[16];
    #pragma unroll
    for (int j = 0; j < 16; j++) {
        float xv = vf[j];
        f1[j] = bfr(xv);
        float r = xv - f1[j];
        f2[j] = bfr(r);
        r2[j] = r - f2[j];
    }
    uint4* A12 = (uint4*)abuf + (size_t)((rg * 2 + ks) * A12BLK + rot * 4);
    #pragma unroll
    for (int c = 0; c < 4; c++)
        A12[c] = make_uint4(pk(f1[2*c], f1[2*c+1]), pk(f1[2*c+8], f1[2*c+9]),
                            pk(f2[2*c], f2[2*c+1]), pk(f2[2*c+8], f2[2*c+9]));
    uint4* A3 = (uint4*)(abuf + A12SZ + (size_t)((rg * 2 + ks) * A3BLK + rot * 4) * 8);
    A3[0] = make_uint4(pk(r2[0], r2[1]),  pk(r2[8],  r2[9]),
                       pk(r2[2], r2[3]),  pk(r2[10], r2[11]));
    A3[1] = make_uint4(pk(r2[4], r2[5]),  pk(r2[12], r2[13]),
                       pk(r2[6], r2[7]),  pk(r2[14], r2[15]));
}

// Kernel 1: bf16 6-product compensated GEMM over ONE K-half of one 128-token
// tile. Same tiling/pipeline as R13 (8 warps, 64x32 warp tile, windowed TwoSum)
// with bf16 operands: same mma count, ~25-40% fewer crossbar bytes.
extern "C" __global__ void __launch_bounds__(THREADS, 1)
gate_partial_kernel(const float* __restrict__ x)
{
    extern __shared__ char smem[];
    const uint32_t sb = smem_u32(smem);
    float* s_sm   = (float*)(smem + SOFF);   // TwoSum high parts: [64][THREADS]
    float* logits = (float*)smem;            // reused after GEMM: [128][LST]

    const int tid  = threadIdx.x;
    const int lane = tid & 31;
    const int warp = tid >> 5;
    const int wm   = warp & 1;       // 2 M groups of 64 rows
    const int wn   = warp >> 1;      // 4 N groups of 32 experts
    const int tile = blockIdx.x >> 1;
    const int half = blockIdx.x & 1;
    const long tokBase = (long)tile * BM;
    const int  g0   = half * NCHALF;

    const float* xp = x + (tokBase + (tid >> 1)) * DIM + g0 * KC + (tid & 1) * 16;

    float w[4][4][4], c[4][4][4];
    #pragma unroll
    for (int i = 0; i < 4; i++)
        #pragma unroll
        for (int j = 0; j < 4; j++)
            #pragma unroll
            for (int k = 0; k < 4; k++) { w[i][j][k] = 0.f; c[i][j][k] = 0.f; }
    #pragma unroll
    for (int j = 0; j < 64; j++) s_sm[j * THREADS + tid] = 0.f;

    // Prologue: stage chunk g0 (A synchronously, B via cp.async)
    {
        float4 v[4];
        #pragma unroll
        for (int j = 0; j < 4; j++) v[j] = *(const float4*)(xp + j * 4);
        store_a(smem, v, tid);
        const char* src = g_Wb + (size_t)g0 * BCH;
        #pragma unroll
        for (int j = 0; j < 4; j++)
            cp_async16(sb + BOFF + (uint32_t)(j * THREADS + tid) * 16,
                       (const uint4*)src + j * THREADS + tid);
        #pragma unroll
        for (int j = 0; j < 2; j++)
            cp_async16(sb + BOFF + B12SZ + (uint32_t)(j * THREADS + tid) * 16,
                       (const uint4*)(src + B12SZ) + j * THREADS + tid);
        CP_COMMIT();
        CP_WAIT0();
    }
    __syncthreads();

    for (int i = 0; i < NCHALF; i++) {
        // Prefetch next chunk: x into registers, B via cp.async
        float4 xa[4];
        if (i + 1 < NCHALF) {
            #pragma unroll
            for (int j = 0; j < 4; j++) xa[j] = *(const float4*)(xp + (i + 1) * KC + j * 4);
            const char* src = g_Wb + (size_t)(g0 + i + 1) * BCH;
            uint32_t bdst = sb + BOFF + (uint32_t)((i + 1) & 1) * BCH;
            #pragma unroll
            for (int j = 0; j < 4; j++)
                cp_async16(bdst + (uint32_t)(j * THREADS + tid) * 16,
                           (const uint4*)src + j * THREADS + tid);
            #pragma unroll
            for (int j = 0; j < 2; j++)
                cp_async16(bdst + B12SZ + (uint32_t)(j * THREADS + tid) * 16,
                           (const uint4*)(src + B12SZ) + j * THREADS + tid);
            CP_COMMIT();
        }

        // Compute chunk i: 2 k16-steps x 6 products x (mt4 x nt4)
        const char* Ab = smem + (i & 1) * ABUF;
        const char* Bb = smem + BOFF + (i & 1) * BCH;
        #pragma unroll
        for (int ks = 0; ks < 2; ks++) {
            uint4 b12[4]; uint2 b3[4];
            #pragma unroll
            for (int nt = 0; nt < 4; nt++) {
                int idx = ((wn * 4 + nt) * 2 + ks) * 32 + lane;
                b12[nt] = ((const uint4*)Bb)[idx];
                b3[nt]  = ((const uint2*)(Bb + B12SZ))[idx];
            }
            const int li = (((lane >> 2) + 2 * ks) & 7) * 4 + (lane & 3);
            uint4 a0_12[4], a1_12[4]; uint2 a0_3[4], a1_3[4];
            #pragma unroll
            for (int mt = 0; mt < 4; mt++) {
                int rg = wm * 8 + mt * 2;
                a0_12[mt] = ((const uint4*)Ab)[(rg * 2 + ks) * A12BLK + li];
                a1_12[mt] = ((const uint4*)Ab)[((rg + 1) * 2 + ks) * A12BLK + li];
                a0_3[mt] = *(const uint2*)(Ab + A12SZ + (size_t)((rg * 2 + ks) * A3BLK + li) * 8);
                a1_3[mt] = *(const uint2*)(Ab + A12SZ + (size_t)(((rg + 1) * 2 + ks) * A3BLK + li) * 8);
            }
            // Sweep 1: A1*B1 -> w
            #pragma unroll
            for (int nt = 0; nt < 4; nt++)
                #pragma unroll
                for (int mt = 0; mt < 4; mt++)
                    mma_bf16(w[mt][nt], a0_12[mt].x, a1_12[mt].x, a0_12[mt].y, a1_12[mt].y,
                             b12[nt].x, b12[nt].y);
            // Sweep 2: A1*B2 -> c
            #pragma unroll
            for (int nt = 0; nt < 4; nt++)
                #pragma unroll
                for (int mt = 0; mt < 4; mt++)
                    mma_bf16(c[mt][nt], a0_12[mt].x, a1_12[mt].x, a0_12[mt].y, a1_12[mt].y,
                             b12[nt].z, b12[nt].w);
            // Sweep 3: A2*B1 -> c
            #pragma unroll
            for (int nt = 0; nt < 4; nt++)
                #pragma unroll
                for (int mt = 0; mt < 4; mt++)
                    mma_bf16(c[mt][nt], a0_12[mt].z, a1_12[mt].z, a0_12[mt].w, a1_12[mt].w,
                             b12[nt].x, b12[nt].y);
            // Sweep 4: A2*B2 -> c
            #pragma unroll
            for (int nt = 0; nt < 4; nt++)
                #pragma unroll
                for (int mt = 0; mt < 4; mt++)
                    mma_bf16(c[mt][nt], a0_12[mt].z, a1_12[mt].z, a0_12[mt].w, a1_12[mt].w,
                             b12[nt].z, b12[nt].w);
            // Sweep 5: A1*B3 -> c
            #pragma unroll
            for (int nt = 0; nt < 4; nt++)
                #pragma unroll
                for (int mt = 0; mt < 4; mt++)
                    mma_bf16(c[mt][nt], a0_12[mt].x, a1_12[mt].x, a0_12[mt].y, a1_12[mt].y,
                             b3[nt].x, b3[nt].y);
            // Sweep 6: A3*B1 -> c
            #pragma unroll
            for (int nt = 0; nt < 4; nt++)
                #pragma unroll
                for (int mt = 0; mt < 4; mt++)
                    mma_bf16(c[mt][nt], a0_3[mt].x, a1_3[mt].x, a0_3[mt].y, a1_3[mt].y,
                             b12[nt].x, b12[nt].y);
        }

        // Split + store the prefetched A registers (LDG latency hidden by mma)
        if (i + 1 < NCHALF)
            store_a(smem + ((i + 1) & 1) * ABUF, xa, tid);

        // Every 8 chunks (256 k-elems window): TwoSum-fold w into (s_sm, c)
        if ((i & 7) == 7) {
            #pragma unroll
            for (int mt = 0; mt < 4; mt++)
                #pragma unroll
                for (int nt = 0; nt < 4; nt++)
                    #pragma unroll
                    for (int k = 0; k < 4; k++) {
                        int j = ((mt * 4 + nt) * 4 + k);
                        float p  = w[mt][nt][k];
                        float sv = s_sm[j * THREADS + tid];
                        float z  = __fadd_rn(sv, p);
                        float t  = __fadd_rn(z, -sv);
                        float e1 = __fadd_rn(p, -t);
                        float t2 = __fadd_rn(z, -t);
                        float e2 = __fadd_rn(sv, -t2);
                        c[mt][nt][k] = __fadd_rn(c[mt][nt][k], __fadd_rn(e1, e2));
                        s_sm[j * THREADS + tid] = z;
                        w[mt][nt][k] = 0.f;
                    }
        }
        CP_WAIT0();
        __syncthreads();
    }

    // Write partial logits (s + c) into smem, then coalesced copy to g_P
    #pragma unroll
    for (int mt = 0; mt < 4; mt++) {
        #pragma unroll
        for (int nt = 0; nt < 4; nt++) {
            int rowb = wm * 64 + mt * 16 + (lane >> 2);
            int colb = wn * 32 + nt * 8 + 2 * (lane & 3);
            #pragma unroll
            for (int hf = 0; hf < 2; hf++) {
                int rw = rowb + hf * 8;
                int j0 = ((mt * 4 + nt) * 4 + 2 * hf);
                float s0 = s_sm[j0 * THREADS + tid];
                float s1 = s_sm[(j0 + 1) * THREADS + tid];
                logits[rw * LST + colb]     = __fadd_rn(s0, c[mt][nt][2*hf]);
                logits[rw * LST + colb + 1] = __fadd_rn(s1, c[mt][nt][2*hf+1]);
            }
        }
    }
    __syncthreads();

    float* Pd = g_P + ((size_t)tile * 2 + half) * (BM * NE);
    #pragma unroll
    for (int j = 0; j < 64; j++) {
        int f = j * THREADS + tid;           // coalesced STG
        Pd[f] = logits[(f >> 7) * LST + (f & 127)];
    }
}

// Kernel 2: combine halves + bias, then the (unchanged) routing epilogue.
extern "C" __global__ void gate_route_kernel(const float* __restrict__ bias,
                                             float* __restrict__ out,
                                             int out_size, int Ttot)
{
    extern __shared__ float logits[];        // [128][LST]
    const int tid  = threadIdx.x;            // 128 threads = 1 per token
    const int tile = blockIdx.x;
    const long tokBase = (long)tile * BM;

    const float4* P0 = (const float4*)(g_P + ((size_t)tile * 2 + 0) * (BM * NE));
    const float4* P1 = (const float4*)(g_P + ((size_t)tile * 2 + 1) * (BM * NE));
    for (int j = 0; j < 32; j++) {
        int f4 = j * 128 + tid;
        float4 a = P0[f4], b = P1[f4];
        int row = f4 >> 5, col = (f4 & 31) * 4;
        logits[row * LST + col]     = a.x + b.x + __ldg(bias + col);
        logits[row * LST + col + 1] = a.y + b.y + __ldg(bias + col + 1);
        logits[row * LST + col + 2] = a.z + b.z + __ldg(bias + col + 2);
        logits[row * LST + col + 3] = a.w + b.w + __ldg(bias + col + 3);
    }
    __syncthreads();

    const float* row = logits + tid * LST;
    float v1[2], v2[2];
    #pragma unroll
    for (int g = 0; g < 2; g++) {
        float b1 = -INFINITY, b2 = -INFINITY;
        for (int j = 0; j < 64; j++) {
            float v = row[g * 64 + j];
            if (v > b1) { b2 = b1; b1 = v; } else if (v > b2) { b2 = v; }
        }
        v1[g] = b1; v2[g] = b2;
    }
    float m = fmaxf(v1[0], v1[1]);
    double s0 = exp((double)v1[0] - (double)m) + exp((double)v2[0] - (double)m);
    double s1 = exp((double)v1[1] - (double)m) + exp((double)v2[1] - (double)m);
    int gsel = (s1 > s0) ? 1 : 0;            // tie -> lower group (matches lax.top_k)
    const float* grow = row + gsel * 64;
    unsigned long long used = 0ull;
    float vals[KSEL]; int ids[KSEL];
    #pragma unroll
    for (int p = 0; p < KSEL; p++) {         // sequential argmax, ties -> lower idx
        float best = -INFINITY; int bi = 0;
        for (int j = 0; j < 64; j++) {
            if (!((used >> j) & 1ull)) {
                float v = grow[j];
                if (v > best) { best = v; bi = j; }
            }
        }
        used |= (1ull << bi);
        vals[p] = best; ids[p] = gsel * 64 + bi;
    }
    float e[KSEL], ssum = 0.f;
    #pragma unroll
    for (int p = 0; p < KSEL; p++) { e[p] = expf(vals[p] - m); ssum += e[p]; }
    ssum = fmaxf(ssum, 1e-9f);
    long tok = tokBase + tid;
    #pragma unroll
    for (int p = 0; p < KSEL; p++) out[tok * KSEL + p] = e[p] / ssum;
    if (out_size >= 2 * Ttot * KSEL) {       // [w ; idx] layout: indices as floats
        float* oi = out + (long)Ttot * KSEL;
        #pragma unroll
        for (int p = 0; p < KSEL; p++) oi[tok * KSEL + p] = (float)ids[p];
    }
}

extern "C" void kernel_launch(void* const* d_in, const int* in_sizes, int n_in,
                              void* d_out, int out_size) {
    const float* x    = (const float*)d_in[0];
    const float* W    = (const float*)d_in[1];
    const float* bias = (const float*)d_in[2];
    float* out = (float*)d_out;

    int Ttot  = in_sizes[0] / DIM;     // 65536
    int tiles = Ttot / BM;             // 512

    cudaFuncSetAttribute((const void*)gate_partial_kernel,
                         cudaFuncAttributeMaxDynamicSharedMemorySize, SMEM_TOTAL);
    cudaFuncSetAttribute((const void*)gate_route_kernel,
                         cudaFuncAttributeMaxDynamicSharedMemorySize, RSMEM);

    prep_w_kernel<<<256, 256>>>(W);
    gate_partial_kernel<<<tiles * 2, THREADS, SMEM_TOTAL>>>(x);
    gate_route_kernel<<<tiles, BM, RSMEM>>>(bias, out, out_size, Ttot);
}